// round 13
// baseline (speedup 1.0000x reference)
#include <cuda_runtime.h>
#include <cuda_bf16.h>
#include <cstdint>
#include <math.h>

#define FEAT 256
#define EMB 512
#define NPTS 32
#define SDIM 16
#define MAX_E 4096
#define MAX_NODES 10000
#define MPAD 10112          // 79 * 128
#define EPS 0.1f
#define MAX_ITER 10
#define PPB 4               // pairs (warps) per block in sinkhorn pass1
#define NU_TILDE 0.03125001f          // 1/32 + 1e-8
#define SCALE 14.426950408889634f     // (1/EPS)*log2(e)
#define K2LOG (-4.9999995385f)        // log2(NU_TILDE)
#define THRESH_SCALED 1.4426950408889634f  // 0.1 * SCALE

// ---------------- scratch (static device globals; no allocs) ----------------
__device__ __align__(256) float         g_z[(size_t)MPAD * EMB];
__device__ __align__(256) __nv_bfloat16 g_xhi[(size_t)MPAD * FEAT];
__device__ __align__(256) __nv_bfloat16 g_xlo[(size_t)MPAD * FEAT];
__device__ __align__(256) __nv_bfloat16 g_wthi[(size_t)EMB * FEAT];   // W^T [n][k]
__device__ __align__(256) __nv_bfloat16 g_wtlo[(size_t)EMB * FEAT];
__device__ __align__(256) float         g_cost[2 * MAX_E * MAX_ITER];
__device__ float  g_err[2 * MAX_ITER];
__device__ double g_accd;

// ---------------- fast math wrappers ----------------------------------------
__device__ __forceinline__ float ex2(float x) {
    float y; asm("ex2.approx.ftz.f32 %0, %1;" : "=f"(y) : "f"(x)); return y;
}
__device__ __forceinline__ float lg2(float x) {
    float y; asm("lg2.approx.ftz.f32 %0, %1;" : "=f"(y) : "f"(x)); return y;
}
__device__ __forceinline__ uint32_t smem_u32(const void* p) {
    uint32_t a;
    asm("{ .reg .u64 t; cvta.to.shared.u64 t, %1; cvt.u32.u64 %0, t; }"
        : "=r"(a) : "l"(p));
    return a;
}

// ---------------- merged convert kernel --------------------------------------
// blocks [0, 128):   W [k][n] -> W^T [n][k] hi/lo via 32x32 smem transpose
// blocks [128, ...): x float4 -> 4x(hi,lo) bf16  (+ accumulator init)
#define WBLOCKS 128
__global__ __launch_bounds__(256) void sge_convert(
    const float* __restrict__ x, const float* __restrict__ W, int M)
{
    __shared__ float tile[32][33];
    if (blockIdx.x < WBLOCKS) {
        const int k0 = (blockIdx.x & 7) * 32, n0 = (blockIdx.x >> 3) * 32;
        const int tx = threadIdx.x & 31, ty4 = threadIdx.x >> 5;  // 8 rows/pass
#pragma unroll
        for (int r = 0; r < 4; r++) {
            int k = ty4 + r * 8;
            tile[k][tx] = W[(size_t)(k0 + k) * EMB + n0 + tx];
        }
        __syncthreads();
#pragma unroll
        for (int r = 0; r < 4; r++) {
            int n = ty4 + r * 8;
            float v = tile[tx][n];
            __nv_bfloat16 hi = __float2bfloat16(v);
            __nv_bfloat16 lo = __float2bfloat16(v - __bfloat162float(hi));
            g_wthi[(size_t)(n0 + n) * FEAT + k0 + tx] = hi;
            g_wtlo[(size_t)(n0 + n) * FEAT + k0 + tx] = lo;
        }
    } else {
        int i = (blockIdx.x - WBLOCKS) * 256 + threadIdx.x;  // group of 4
        if (i < 2 * MAX_ITER) g_err[i] = 0.f;
        if (i == 2 * MAX_ITER) g_accd = 0.0;
        if (i >= (MPAD * FEAT) / 4) return;
        int row = (i * 4) / FEAT;
        float4 v = make_float4(0.f, 0.f, 0.f, 0.f);
        if (row < M) v = *(const float4*)(x + (size_t)i * 4);
        __nv_bfloat16 h[4], l[4];
        float vv[4] = {v.x, v.y, v.z, v.w};
#pragma unroll
        for (int q = 0; q < 4; q++) {
            h[q] = __float2bfloat16(vv[q]);
            l[q] = __float2bfloat16(vv[q] - __bfloat162float(h[q]));
        }
        *(uint2*)(g_xhi + (size_t)i * 4) = *(uint2*)h;
        *(uint2*)(g_xlo + (size_t)i * 4) = *(uint2*)l;
    }
}

// ---------------- HMMA GEMM: z = x @ W via bf16 hi/lo split -----------------
__device__ __forceinline__ void mma16816(
    float& c0, float& c1, float& c2, float& c3,
    uint32_t a0, uint32_t a1, uint32_t a2, uint32_t a3,
    uint32_t b0, uint32_t b1)
{
    asm volatile(
        "mma.sync.aligned.m16n8k16.row.col.f32.bf16.bf16.f32 "
        "{%0,%1,%2,%3}, {%4,%5,%6,%7}, {%8,%9}, {%0,%1,%2,%3};\n"
        : "+f"(c0), "+f"(c1), "+f"(c2), "+f"(c3)
        : "r"(a0), "r"(a1), "r"(a2), "r"(a3), "r"(b0), "r"(b1));
}

#define LDM4(r, a) \
    asm volatile("ldmatrix.sync.aligned.m8n8.x4.shared.b16 {%0,%1,%2,%3}, [%4];" \
        : "=r"((r)[0]), "=r"((r)[1]), "=r"((r)[2]), "=r"((r)[3]) : "r"(a))

#define KC 32
#define ROWB 80                 // 80B smem rows (ldmatrix conflict-free)
#define TILE_BYTES (128 * ROWB)       // 10240
#define STAGE_BYTES (4 * TILE_BYTES)  // 40960

__device__ __forceinline__ void cp_tile(uint32_t sbase,
    const __nv_bfloat16* __restrict__ g, int row0, int c0, int tid)
{
#pragma unroll
    for (int l = 0; l < 2; l++) {
        int id = l * 256 + tid;
        int r = id >> 2, s = id & 3;
        const void* src = g + (size_t)(row0 + r) * FEAT + c0 * KC + s * 8;
        uint32_t dst = sbase + r * ROWB + s * 16;
        asm volatile("cp.async.cg.shared.global [%0], [%1], 16;"
                     :: "r"(dst), "l"(src));
    }
}

__global__ __launch_bounds__(256, 2) void sge_gemm_mma(int M)
{
    extern __shared__ char gsm[];
    uint32_t sb = smem_u32(gsm);
    const int tid = threadIdx.x;
    const int wid = tid >> 5, lane = tid & 31;
    const int g = lane >> 2, t = lane & 3;
    const int wm = wid & 1, wn = wid >> 1;
    const int M0 = blockIdx.y * 128, N0 = blockIdx.x * 128;
    const int warpM = wm * 64, warpN = wn * 32;

    const uint32_t loff = (uint32_t)((lane & 15) * ROWB + (lane >> 4) * 16);

    float acc[4][4][4];
#pragma unroll
    for (int mi = 0; mi < 4; mi++)
#pragma unroll
        for (int ni = 0; ni < 4; ni++)
#pragma unroll
            for (int r = 0; r < 4; r++) acc[mi][ni][r] = 0.f;

    cp_tile(sb + 0 * TILE_BYTES, g_xhi,  M0, 0, tid);
    cp_tile(sb + 1 * TILE_BYTES, g_xlo,  M0, 0, tid);
    cp_tile(sb + 2 * TILE_BYTES, g_wthi, N0, 0, tid);
    cp_tile(sb + 3 * TILE_BYTES, g_wtlo, N0, 0, tid);
    asm volatile("cp.async.commit_group;");

    for (int c = 0; c < FEAT / KC; c++) {
        if (c < FEAT / KC - 1) {
            uint32_t nb = sb + ((c + 1) & 1) * STAGE_BYTES;
            cp_tile(nb + 0 * TILE_BYTES, g_xhi,  M0, c + 1, tid);
            cp_tile(nb + 1 * TILE_BYTES, g_xlo,  M0, c + 1, tid);
            cp_tile(nb + 2 * TILE_BYTES, g_wthi, N0, c + 1, tid);
            cp_tile(nb + 3 * TILE_BYTES, g_wtlo, N0, c + 1, tid);
            asm volatile("cp.async.commit_group;");
            asm volatile("cp.async.wait_group 1;");
        } else {
            asm volatile("cp.async.wait_group 0;");
        }
        __syncthreads();

        const uint32_t stage = sb + (c & 1) * STAGE_BYTES;
        const uint32_t ahA = stage + 0 * TILE_BYTES + warpM * ROWB + loff;
        const uint32_t alA = stage + 1 * TILE_BYTES + warpM * ROWB + loff;
        const uint32_t bhA = stage + 2 * TILE_BYTES + warpN * ROWB + loff;
        const uint32_t blA = stage + 3 * TILE_BYTES + warpN * ROWB + loff;

#pragma unroll
        for (int ks = 0; ks < 2; ks++) {
            const uint32_t ko = ks * 32;
            uint32_t bh[2][4], bl[2][4];
            LDM4(bh[0], bhA + 0 * 16 * ROWB + ko);
            LDM4(bh[1], bhA + 1 * 16 * ROWB + ko);
            LDM4(bl[0], blA + 0 * 16 * ROWB + ko);
            LDM4(bl[1], blA + 1 * 16 * ROWB + ko);
            uint32_t ah[4][4];
#pragma unroll
            for (int mi = 0; mi < 4; mi++)
                LDM4(ah[mi], ahA + mi * 16 * ROWB + ko);
#pragma unroll
            for (int mi = 0; mi < 4; mi++)
#pragma unroll
                for (int ni = 0; ni < 4; ni++) {
                    const int np = ni >> 1, no = ni & 1;
                    mma16816(acc[mi][ni][0], acc[mi][ni][1], acc[mi][ni][2], acc[mi][ni][3],
                             ah[mi][0], ah[mi][1], ah[mi][2], ah[mi][3],
                             bh[np][no], bh[np][no + 2]);
                    mma16816(acc[mi][ni][0], acc[mi][ni][1], acc[mi][ni][2], acc[mi][ni][3],
                             ah[mi][0], ah[mi][1], ah[mi][2], ah[mi][3],
                             bl[np][no], bl[np][no + 2]);
                }
            uint32_t al[4][4];
#pragma unroll
            for (int mi = 0; mi < 4; mi++)
                LDM4(al[mi], alA + mi * 16 * ROWB + ko);
#pragma unroll
            for (int mi = 0; mi < 4; mi++)
#pragma unroll
                for (int ni = 0; ni < 4; ni++) {
                    const int np = ni >> 1, no = ni & 1;
                    mma16816(acc[mi][ni][0], acc[mi][ni][1], acc[mi][ni][2], acc[mi][ni][3],
                             al[mi][0], al[mi][1], al[mi][2], al[mi][3],
                             bh[np][no], bh[np][no + 2]);
                }
        }
        __syncthreads();
    }

#pragma unroll
    for (int mi = 0; mi < 4; mi++) {
        int r0 = M0 + warpM + mi * 16 + g;
#pragma unroll
        for (int ni = 0; ni < 4; ni++) {
            int col = N0 + warpN + ni * 8 + 2 * t;
            if (r0 < M)
                *(float2*)&g_z[(size_t)r0 * EMB + col] =
                    make_float2(acc[mi][ni][0], acc[mi][ni][1]);
            if (r0 + 8 < M)
                *(float2*)&g_z[(size_t)(r0 + 8) * EMB + col] =
                    make_float2(acc[mi][ni][2], acc[mi][ni][3]);
        }
    }
}

// ---------------- pass 1: log2-domain Sinkhorn (smem C row+col copies) -------
__global__ __launch_bounds__(128, 5) void sge_sinkhorn_pass1(
    const int* __restrict__ ep, const int* __restrict__ en, int E)
{
    __shared__ __align__(16) float Csh[PPB][NPTS][36];   // row-major (u-half)
    __shared__ __align__(16) float CshT[PPB][NPTS][36];  // transposed (v-half)
    __shared__ __align__(16) float vsh[PPB][NPTS];
    __shared__ __align__(16) float ush[PPB][NPTS];
    __shared__ __align__(16) float redsh[PPB][2][MAX_ITER][8];  // 8 partials
    const int warp = threadIdx.x >> 5, lane = threadIdx.x & 31;
    const int p = blockIdx.x * PPB + warp;
    if (p >= 2 * E) return;
    const int batch = (p >= E) ? 1 : 0;
    const int e = p - batch * E;
    const int* edges = batch ? en : ep;
    const int nx = edges[e];
    const int ny = edges[E + e];

    float (*bsh)[SDIM] = (float(*)[SDIM]) & Csh[warp][0][0];  // setup overlay

    float a[SDIM];
    {
        const float4* ap = (const float4*)(g_z + (size_t)nx * EMB + lane * SDIM);
        const float4* bp = (const float4*)(g_z + (size_t)ny * EMB + lane * SDIM);
#pragma unroll
        for (int q = 0; q < 4; q++) {
            float4 av = ap[q];
            a[q * 4 + 0] = av.x; a[q * 4 + 1] = av.y;
            a[q * 4 + 2] = av.z; a[q * 4 + 3] = av.w;
            *(float4*)&bsh[lane][q * 4] = bp[q];
        }
    }
    __syncwarp();

    // C2row in regs only during setup (dead after transpose stores)
    float C2row[NPTS];
#pragma unroll 8
    for (int j = 0; j < NPTS; j++) {
        float c = 0.f;
#pragma unroll
        for (int d = 0; d < SDIM; d++) {
            float df = a[d] - bsh[j][d];
            c = fmaf(df, df, c);
        }
        C2row[j] = c * SCALE;
        CshT[warp][j][lane] = C2row[j];   // conflict-free (bank = lane + 4j)
    }
    __syncwarp();   // bsh reads done before overwriting Csh
#pragma unroll
    for (int g4 = 0; g4 < 8; g4++)
        *(float4*)&Csh[warp][lane][g4 * 4] =
            make_float4(C2row[g4 * 4 + 0], C2row[g4 * 4 + 1],
                        C2row[g4 * 4 + 2], C2row[g4 * 4 + 3]);
    __syncwarp();

    float U = 0.f, V = 0.f;

    for (int t = 0; t < MAX_ITER; t++) {
        vsh[warp][lane] = V;
        __syncwarp();
        // ---- u-half: U_i = K2 - (m + log2 sum_j 2^(V_j - C2_ij - m)) ----
        float ma = -1e30f, mb = -1e30f;
#pragma unroll
        for (int j4 = 0; j4 < 8; j4 += 2) {
            float4 va = *(const float4*)&vsh[warp][j4 * 4];
            float4 vb = *(const float4*)&vsh[warp][j4 * 4 + 4];
            float4 ca = *(const float4*)&Csh[warp][lane][j4 * 4];
            float4 cb = *(const float4*)&Csh[warp][lane][j4 * 4 + 4];
            ma = fmaxf(ma, fmaxf(fmaxf(va.x - ca.x, va.y - ca.y),
                                 fmaxf(va.z - ca.z, va.w - ca.w)));
            mb = fmaxf(mb, fmaxf(fmaxf(vb.x - cb.x, vb.y - cb.y),
                                 fmaxf(vb.z - cb.z, vb.w - cb.w)));
        }
        float m = fmaxf(ma, mb);
        float sa = 0.f, sb2 = 0.f;
#pragma unroll
        for (int j4 = 0; j4 < 8; j4 += 2) {
            float4 va = *(const float4*)&vsh[warp][j4 * 4];
            float4 vb = *(const float4*)&vsh[warp][j4 * 4 + 4];
            float4 ca = *(const float4*)&Csh[warp][lane][j4 * 4];
            float4 cb = *(const float4*)&Csh[warp][lane][j4 * 4 + 4];
            float e0 = ex2(va.x - ca.x - m);
            float e1 = ex2(va.y - ca.y - m);
            float e2 = ex2(va.z - ca.z - m);
            float e3 = ex2(va.w - ca.w - m);
            float f0 = ex2(vb.x - cb.x - m);
            float f1 = ex2(vb.y - cb.y - m);
            float f2 = ex2(vb.z - cb.z - m);
            float f3 = ex2(vb.w - cb.w - m);
            sa  += (e0 + e1) + (e2 + e3);
            sb2 += (f0 + f1) + (f2 + f3);
        }
        float Unew = K2LOG - (m + lg2(sa + sb2));
        float dU = fabsf(Unew - U);
        U = Unew;
        // shallow (2-step) reduction -> 8 partials; STS-only consumers
        dU += __shfl_xor_sync(0xffffffffu, dU, 1);
        dU += __shfl_xor_sync(0xffffffffu, dU, 2);
        if ((lane & 3) == 0) redsh[warp][0][t][lane >> 2] = dU;
        ush[warp][lane] = U;
        __syncwarp();
        // ---- v-half (lane = column j) with fused cost ----
        float m2a = -1e30f, m2b = -1e30f;
#pragma unroll
        for (int i4 = 0; i4 < 8; i4 += 2) {
            float4 ua = *(const float4*)&ush[warp][i4 * 4];
            float4 ub = *(const float4*)&ush[warp][i4 * 4 + 4];
            float4 ca = *(const float4*)&CshT[warp][lane][i4 * 4];
            float4 cb = *(const float4*)&CshT[warp][lane][i4 * 4 + 4];
            m2a = fmaxf(m2a, fmaxf(fmaxf(ua.x - ca.x, ua.y - ca.y),
                                   fmaxf(ua.z - ca.z, ua.w - ca.w)));
            m2b = fmaxf(m2b, fmaxf(fmaxf(ub.x - cb.x, ub.y - cb.y),
                                   fmaxf(ub.z - cb.z, ub.w - cb.w)));
        }
        float m2 = fmaxf(m2a, m2b);
        float s2a = 0.f, s2b = 0.f, sca = 0.f, scb = 0.f;
#pragma unroll
        for (int i4 = 0; i4 < 8; i4 += 2) {
            float4 ua = *(const float4*)&ush[warp][i4 * 4];
            float4 ub = *(const float4*)&ush[warp][i4 * 4 + 4];
            float4 ca = *(const float4*)&CshT[warp][lane][i4 * 4];
            float4 cb = *(const float4*)&CshT[warp][lane][i4 * 4 + 4];
            float e0 = ex2(ua.x - ca.x - m2);
            float e1 = ex2(ua.y - ca.y - m2);
            float e2 = ex2(ua.z - ca.z - m2);
            float e3 = ex2(ua.w - ca.w - m2);
            float f0 = ex2(ub.x - cb.x - m2);
            float f1 = ex2(ub.y - cb.y - m2);
            float f2 = ex2(ub.z - cb.z - m2);
            float f3 = ex2(ub.w - cb.w - m2);
            s2a += (e0 + e1) + (e2 + e3);
            s2b += (f0 + f1) + (f2 + f3);
            sca += fmaf(e0, ca.x, e1 * ca.y) + fmaf(e2, ca.z, e3 * ca.w);
            scb += fmaf(f0, cb.x, f1 * cb.y) + fmaf(f2, cb.z, f3 * cb.w);
        }
        float s2 = s2a + s2b;
        V = K2LOG - (m2 + lg2(s2));
        float costl = NU_TILDE * __fdividef(sca + scb, s2 * SCALE);
        costl += __shfl_xor_sync(0xffffffffu, costl, 1);
        costl += __shfl_xor_sync(0xffffffffu, costl, 2);
        if ((lane & 3) == 0) redsh[warp][1][t][lane >> 2] = costl;
    }
    __syncwarp();

    if (lane < 2 * MAX_ITER) {
        const int which = (lane < MAX_ITER) ? 0 : 1;
        const int t = (lane < MAX_ITER) ? lane : lane - MAX_ITER;
        float ssum = 0.f;
#pragma unroll
        for (int i = 0; i < 8; i++) ssum += redsh[warp][which][t][i];
        if (which == 0) atomicAdd(&g_err[batch * MAX_ITER + t], ssum);
        else            g_cost[p * MAX_ITER + t] = ssum;
    }
}

// ---------------- reduce: pick iteration T-1 cost, accumulate loss -----------
__global__ __launch_bounds__(256) void sge_reduce(int E)
{
    __shared__ double sd[256];
    __shared__ int Tsh[2];
    if (threadIdx.x < 2) {
        int b = threadIdx.x;
        int T = MAX_ITER;
        float invE = 1.0f / (float)E;
        for (int t = 0; t < MAX_ITER; t++)
            if (g_err[b * MAX_ITER + t] * invE < THRESH_SCALED) { T = t + 1; break; }
        Tsh[b] = T;
    }
    __syncthreads();
    int p = blockIdx.x * 256 + threadIdx.x;
    double con = 0.0;
    if (p < 2 * E) {
        int b = (p >= E) ? 1 : 0;
        float c = g_cost[p * MAX_ITER + Tsh[b] - 1];
        float energy = -c;
        con = b ? (double)__expf(energy) : (double)energy * (double)energy;
    }
    sd[threadIdx.x] = con;
    __syncthreads();
    for (int s2 = 128; s2; s2 >>= 1) {
        if (threadIdx.x < s2) sd[threadIdx.x] += sd[threadIdx.x + s2];
        __syncthreads();
    }
    if (threadIdx.x == 0) atomicAdd(&g_accd, sd[0]);
}

// ---------------- finalize ---------------------------------------------------
__global__ void sge_finalize_kernel(float* out, int out_size, int E)
{
    float loss = (float)(g_accd / (double)E);
    for (int i = threadIdx.x; i < out_size; i += blockDim.x) out[i] = loss;
}

// ---------------- launch -----------------------------------------------------
extern "C" void kernel_launch(void* const* d_in, const int* in_sizes, int n_in,
                              void* d_out, int out_size)
{
    const float* x = (const float*)d_in[0];
    const float* W = (const float*)d_in[1];
    const int* ep  = (const int*)d_in[2];
    const int* en  = (const int*)d_in[3];
    int M = in_sizes[0] / FEAT;
    if (M > MAX_NODES) M = MAX_NODES;
    int E = in_sizes[2] / 2;
    if (E > MAX_E) E = MAX_E;

    cudaFuncSetAttribute(sge_gemm_mma,
                         cudaFuncAttributeMaxDynamicSharedMemorySize,
                         2 * STAGE_BYTES);

    int xblocks = (MPAD * FEAT / 4 + 255) / 256;
    sge_convert<<<WBLOCKS + xblocks, 256>>>(x, W, M);
    sge_gemm_mma<<<dim3(EMB / 128, MPAD / 128), 256, 2 * STAGE_BYTES>>>(M);
    int nblocks = (2 * E + PPB - 1) / PPB;
    sge_sinkhorn_pass1<<<nblocks, 128>>>(ep, en, E);
    sge_reduce<<<(2 * E + 255) / 256, 256>>>(E);
    sge_finalize_kernel<<<1, 32>>>((float*)d_out, out_size, E);
}

// round 14
// speedup vs baseline: 1.0431x; 1.0431x over previous
#include <cuda_runtime.h>
#include <cuda_bf16.h>
#include <cstdint>
#include <math.h>

#define FEAT 256
#define EMB 512
#define NPTS 32
#define SDIM 16
#define MAX_E 4096
#define MAX_NODES 10000
#define MPAD 10112          // 79 * 128
#define EPS 0.1f
#define MAX_ITER 10
#define PPB 4               // pairs (warps) per block in sinkhorn pass1
#define NU_TILDE 0.03125001f          // 1/32 + 1e-8
#define SCALE 14.426950408889634f     // (1/EPS)*log2(e)
#define K2LOG (-4.9999995385f)        // log2(NU_TILDE)
#define THRESH_SCALED 1.4426950408889634f  // 0.1 * SCALE

// ---------------- scratch (static device globals; no allocs) ----------------
__device__ __align__(256) float         g_z[(size_t)MPAD * EMB];
__device__ __align__(256) __nv_bfloat16 g_xhi[(size_t)MPAD * FEAT];
__device__ __align__(256) __nv_bfloat16 g_xlo[(size_t)MPAD * FEAT];
__device__ __align__(256) __nv_bfloat16 g_wthi[(size_t)EMB * FEAT];   // W^T [n][k]
__device__ __align__(256) __nv_bfloat16 g_wtlo[(size_t)EMB * FEAT];
__device__ __align__(256) float         g_cost[2 * MAX_E * MAX_ITER];
__device__ float        g_err[2 * MAX_ITER];
__device__ double       g_accd;
__device__ unsigned int g_done;

// ---------------- fast math wrappers ----------------------------------------
__device__ __forceinline__ float ex2(float x) {
    float y; asm("ex2.approx.ftz.f32 %0, %1;" : "=f"(y) : "f"(x)); return y;
}
__device__ __forceinline__ float lg2(float x) {
    float y; asm("lg2.approx.ftz.f32 %0, %1;" : "=f"(y) : "f"(x)); return y;
}
__device__ __forceinline__ uint32_t smem_u32(const void* p) {
    uint32_t a;
    asm("{ .reg .u64 t; cvta.to.shared.u64 t, %1; cvt.u32.u64 %0, t; }"
        : "=r"(a) : "l"(p));
    return a;
}

// ---------------- merged convert kernel --------------------------------------
// blocks [0, 128):   W [k][n] -> W^T [n][k] hi/lo via 32x32 smem transpose
// blocks [128, ...): x float4 -> 4x(hi,lo) bf16  (+ accumulator init)
#define WBLOCKS 128
__global__ __launch_bounds__(256) void sge_convert(
    const float* __restrict__ x, const float* __restrict__ W, int M)
{
    __shared__ float tile[32][33];
    if (blockIdx.x < WBLOCKS) {
        const int k0 = (blockIdx.x & 7) * 32, n0 = (blockIdx.x >> 3) * 32;
        const int tx = threadIdx.x & 31, ty4 = threadIdx.x >> 5;  // 8 rows/pass
#pragma unroll
        for (int r = 0; r < 4; r++) {
            int k = ty4 + r * 8;
            tile[k][tx] = W[(size_t)(k0 + k) * EMB + n0 + tx];
        }
        __syncthreads();
#pragma unroll
        for (int r = 0; r < 4; r++) {
            int n = ty4 + r * 8;
            float v = tile[tx][n];
            __nv_bfloat16 hi = __float2bfloat16(v);
            __nv_bfloat16 lo = __float2bfloat16(v - __bfloat162float(hi));
            g_wthi[(size_t)(n0 + n) * FEAT + k0 + tx] = hi;
            g_wtlo[(size_t)(n0 + n) * FEAT + k0 + tx] = lo;
        }
    } else {
        int i = (blockIdx.x - WBLOCKS) * 256 + threadIdx.x;  // group of 4
        if (i < 2 * MAX_ITER) g_err[i] = 0.f;
        if (i == 2 * MAX_ITER) g_accd = 0.0;
        if (i == 2 * MAX_ITER + 1) g_done = 0u;
        if (i >= (MPAD * FEAT) / 4) return;
        int row = (i * 4) / FEAT;
        float4 v = make_float4(0.f, 0.f, 0.f, 0.f);
        if (row < M) v = *(const float4*)(x + (size_t)i * 4);
        __nv_bfloat16 h[4], l[4];
        float vv[4] = {v.x, v.y, v.z, v.w};
#pragma unroll
        for (int q = 0; q < 4; q++) {
            h[q] = __float2bfloat16(vv[q]);
            l[q] = __float2bfloat16(vv[q] - __bfloat162float(h[q]));
        }
        *(uint2*)(g_xhi + (size_t)i * 4) = *(uint2*)h;
        *(uint2*)(g_xlo + (size_t)i * 4) = *(uint2*)l;
    }
}

// ---------------- HMMA GEMM: z = x @ W via bf16 hi/lo split -----------------
__device__ __forceinline__ void mma16816(
    float& c0, float& c1, float& c2, float& c3,
    uint32_t a0, uint32_t a1, uint32_t a2, uint32_t a3,
    uint32_t b0, uint32_t b1)
{
    asm volatile(
        "mma.sync.aligned.m16n8k16.row.col.f32.bf16.bf16.f32 "
        "{%0,%1,%2,%3}, {%4,%5,%6,%7}, {%8,%9}, {%0,%1,%2,%3};\n"
        : "+f"(c0), "+f"(c1), "+f"(c2), "+f"(c3)
        : "r"(a0), "r"(a1), "r"(a2), "r"(a3), "r"(b0), "r"(b1));
}

#define LDM4(r, a) \
    asm volatile("ldmatrix.sync.aligned.m8n8.x4.shared.b16 {%0,%1,%2,%3}, [%4];" \
        : "=r"((r)[0]), "=r"((r)[1]), "=r"((r)[2]), "=r"((r)[3]) : "r"(a))

#define KC 32
#define ROWB 80                 // 80B smem rows (ldmatrix conflict-free)
#define TILE_BYTES (128 * ROWB)       // 10240
#define STAGE_BYTES (4 * TILE_BYTES)  // 40960

__device__ __forceinline__ void cp_tile(uint32_t sbase,
    const __nv_bfloat16* __restrict__ g, int row0, int c0, int tid)
{
#pragma unroll
    for (int l = 0; l < 2; l++) {
        int id = l * 256 + tid;
        int r = id >> 2, s = id & 3;
        const void* src = g + (size_t)(row0 + r) * FEAT + c0 * KC + s * 8;
        uint32_t dst = sbase + r * ROWB + s * 16;
        asm volatile("cp.async.cg.shared.global [%0], [%1], 16;"
                     :: "r"(dst), "l"(src));
    }
}

__global__ __launch_bounds__(256, 2) void sge_gemm_mma(int M)
{
    extern __shared__ char gsm[];
    uint32_t sb = smem_u32(gsm);
    const int tid = threadIdx.x;
    const int wid = tid >> 5, lane = tid & 31;
    const int g = lane >> 2, t = lane & 3;
    const int wm = wid & 1, wn = wid >> 1;
    const int M0 = blockIdx.y * 128, N0 = blockIdx.x * 128;
    const int warpM = wm * 64, warpN = wn * 32;

    const uint32_t loff = (uint32_t)((lane & 15) * ROWB + (lane >> 4) * 16);

    float acc[4][4][4];
#pragma unroll
    for (int mi = 0; mi < 4; mi++)
#pragma unroll
        for (int ni = 0; ni < 4; ni++)
#pragma unroll
            for (int r = 0; r < 4; r++) acc[mi][ni][r] = 0.f;

    cp_tile(sb + 0 * TILE_BYTES, g_xhi,  M0, 0, tid);
    cp_tile(sb + 1 * TILE_BYTES, g_xlo,  M0, 0, tid);
    cp_tile(sb + 2 * TILE_BYTES, g_wthi, N0, 0, tid);
    cp_tile(sb + 3 * TILE_BYTES, g_wtlo, N0, 0, tid);
    asm volatile("cp.async.commit_group;");

    for (int c = 0; c < FEAT / KC; c++) {
        if (c < FEAT / KC - 1) {
            uint32_t nb = sb + ((c + 1) & 1) * STAGE_BYTES;
            cp_tile(nb + 0 * TILE_BYTES, g_xhi,  M0, c + 1, tid);
            cp_tile(nb + 1 * TILE_BYTES, g_xlo,  M0, c + 1, tid);
            cp_tile(nb + 2 * TILE_BYTES, g_wthi, N0, c + 1, tid);
            cp_tile(nb + 3 * TILE_BYTES, g_wtlo, N0, c + 1, tid);
            asm volatile("cp.async.commit_group;");
            asm volatile("cp.async.wait_group 1;");
        } else {
            asm volatile("cp.async.wait_group 0;");
        }
        __syncthreads();

        const uint32_t stage = sb + (c & 1) * STAGE_BYTES;
        const uint32_t ahA = stage + 0 * TILE_BYTES + warpM * ROWB + loff;
        const uint32_t alA = stage + 1 * TILE_BYTES + warpM * ROWB + loff;
        const uint32_t bhA = stage + 2 * TILE_BYTES + warpN * ROWB + loff;
        const uint32_t blA = stage + 3 * TILE_BYTES + warpN * ROWB + loff;

#pragma unroll
        for (int ks = 0; ks < 2; ks++) {
            const uint32_t ko = ks * 32;
            uint32_t bh[2][4], bl[2][4];
            LDM4(bh[0], bhA + 0 * 16 * ROWB + ko);
            LDM4(bh[1], bhA + 1 * 16 * ROWB + ko);
            LDM4(bl[0], blA + 0 * 16 * ROWB + ko);
            LDM4(bl[1], blA + 1 * 16 * ROWB + ko);
            uint32_t ah[4][4];
#pragma unroll
            for (int mi = 0; mi < 4; mi++)
                LDM4(ah[mi], ahA + mi * 16 * ROWB + ko);
#pragma unroll
            for (int mi = 0; mi < 4; mi++)
#pragma unroll
                for (int ni = 0; ni < 4; ni++) {
                    const int np = ni >> 1, no = ni & 1;
                    mma16816(acc[mi][ni][0], acc[mi][ni][1], acc[mi][ni][2], acc[mi][ni][3],
                             ah[mi][0], ah[mi][1], ah[mi][2], ah[mi][3],
                             bh[np][no], bh[np][no + 2]);
                    mma16816(acc[mi][ni][0], acc[mi][ni][1], acc[mi][ni][2], acc[mi][ni][3],
                             ah[mi][0], ah[mi][1], ah[mi][2], ah[mi][3],
                             bl[np][no], bl[np][no + 2]);
                }
            uint32_t al[4][4];
#pragma unroll
            for (int mi = 0; mi < 4; mi++)
                LDM4(al[mi], alA + mi * 16 * ROWB + ko);
#pragma unroll
            for (int mi = 0; mi < 4; mi++)
#pragma unroll
                for (int ni = 0; ni < 4; ni++) {
                    const int np = ni >> 1, no = ni & 1;
                    mma16816(acc[mi][ni][0], acc[mi][ni][1], acc[mi][ni][2], acc[mi][ni][3],
                             al[mi][0], al[mi][1], al[mi][2], al[mi][3],
                             bh[np][no], bh[np][no + 2]);
                }
        }
        __syncthreads();
    }

#pragma unroll
    for (int mi = 0; mi < 4; mi++) {
        int r0 = M0 + warpM + mi * 16 + g;
#pragma unroll
        for (int ni = 0; ni < 4; ni++) {
            int col = N0 + warpN + ni * 8 + 2 * t;
            if (r0 < M)
                *(float2*)&g_z[(size_t)r0 * EMB + col] =
                    make_float2(acc[mi][ni][0], acc[mi][ni][1]);
            if (r0 + 8 < M)
                *(float2*)&g_z[(size_t)(r0 + 8) * EMB + col] =
                    make_float2(acc[mi][ni][2], acc[mi][ni][3]);
        }
    }
}

// ---------------- pass 1: log2-domain Sinkhorn (R10 configuration) -----------
__global__ __launch_bounds__(128) void sge_sinkhorn_pass1(
    const int* __restrict__ ep, const int* __restrict__ en, int E)
{
    __shared__ __align__(16) float CshT[PPB][NPTS][36];
    __shared__ __align__(16) float vsh[PPB][NPTS];
    __shared__ __align__(16) float ush[PPB][NPTS];
    __shared__ __align__(16) float redsh[PPB][2][MAX_ITER][33];
    const int warp = threadIdx.x >> 5, lane = threadIdx.x & 31;
    const int p = blockIdx.x * PPB + warp;
    if (p >= 2 * E) return;
    const int batch = (p >= E) ? 1 : 0;
    const int e = p - batch * E;
    const int* edges = batch ? en : ep;
    const int nx = edges[e];
    const int ny = edges[E + e];

    float (*bsh)[SDIM] = (float(*)[SDIM]) & CshT[warp][0][0];

    float a[SDIM];
    {
        const float4* ap = (const float4*)(g_z + (size_t)nx * EMB + lane * SDIM);
        const float4* bp = (const float4*)(g_z + (size_t)ny * EMB + lane * SDIM);
#pragma unroll
        for (int q = 0; q < 4; q++) {
            float4 av = ap[q];
            a[q * 4 + 0] = av.x; a[q * 4 + 1] = av.y;
            a[q * 4 + 2] = av.z; a[q * 4 + 3] = av.w;
            *(float4*)&bsh[lane][q * 4] = bp[q];
        }
    }
    __syncwarp();

    float C2row[NPTS];
#pragma unroll 8
    for (int j = 0; j < NPTS; j++) {
        float c = 0.f;
#pragma unroll
        for (int d = 0; d < SDIM; d++) {
            float df = a[d] - bsh[j][d];
            c = fmaf(df, df, c);
        }
        C2row[j] = c * SCALE;
    }
    __syncwarp();
#pragma unroll
    for (int j = 0; j < NPTS; j++) CshT[warp][j][lane] = C2row[j];

    float U = 0.f, V = 0.f;

    for (int t = 0; t < MAX_ITER; t++) {
        vsh[warp][lane] = V;
        __syncwarp();
        float ma = -1e30f, mb = -1e30f;
#pragma unroll
        for (int j4 = 0; j4 < 8; j4 += 2) {
            float4 va = *(const float4*)&vsh[warp][j4 * 4];
            float4 vb = *(const float4*)&vsh[warp][j4 * 4 + 4];
            ma = fmaxf(ma, fmaxf(fmaxf(va.x - C2row[j4 * 4 + 0], va.y - C2row[j4 * 4 + 1]),
                                 fmaxf(va.z - C2row[j4 * 4 + 2], va.w - C2row[j4 * 4 + 3])));
            mb = fmaxf(mb, fmaxf(fmaxf(vb.x - C2row[j4 * 4 + 4], vb.y - C2row[j4 * 4 + 5]),
                                 fmaxf(vb.z - C2row[j4 * 4 + 6], vb.w - C2row[j4 * 4 + 7])));
        }
        float m = fmaxf(ma, mb);
        float sa = 0.f, sb = 0.f;
#pragma unroll
        for (int j4 = 0; j4 < 8; j4 += 2) {
            float4 va = *(const float4*)&vsh[warp][j4 * 4];
            float4 vb = *(const float4*)&vsh[warp][j4 * 4 + 4];
            float e0 = ex2(va.x - C2row[j4 * 4 + 0] - m);
            float e1 = ex2(va.y - C2row[j4 * 4 + 1] - m);
            float e2 = ex2(va.z - C2row[j4 * 4 + 2] - m);
            float e3 = ex2(va.w - C2row[j4 * 4 + 3] - m);
            float f0 = ex2(vb.x - C2row[j4 * 4 + 4] - m);
            float f1 = ex2(vb.y - C2row[j4 * 4 + 5] - m);
            float f2 = ex2(vb.z - C2row[j4 * 4 + 6] - m);
            float f3 = ex2(vb.w - C2row[j4 * 4 + 7] - m);
            sa += (e0 + e1) + (e2 + e3);
            sb += (f0 + f1) + (f2 + f3);
        }
        float Unew = K2LOG - (m + lg2(sa + sb));
        float dU = fabsf(Unew - U);
        U = Unew;
        redsh[warp][0][t][lane] = dU;
        ush[warp][lane] = U;
        __syncwarp();
        float m2a = -1e30f, m2b = -1e30f;
#pragma unroll
        for (int i4 = 0; i4 < 8; i4 += 2) {
            float4 ua = *(const float4*)&ush[warp][i4 * 4];
            float4 ub = *(const float4*)&ush[warp][i4 * 4 + 4];
            float4 ca = *(const float4*)&CshT[warp][lane][i4 * 4];
            float4 cb = *(const float4*)&CshT[warp][lane][i4 * 4 + 4];
            m2a = fmaxf(m2a, fmaxf(fmaxf(ua.x - ca.x, ua.y - ca.y),
                                   fmaxf(ua.z - ca.z, ua.w - ca.w)));
            m2b = fmaxf(m2b, fmaxf(fmaxf(ub.x - cb.x, ub.y - cb.y),
                                   fmaxf(ub.z - cb.z, ub.w - cb.w)));
        }
        float m2 = fmaxf(m2a, m2b);
        float s2a = 0.f, s2b = 0.f, sca = 0.f, scb = 0.f;
#pragma unroll
        for (int i4 = 0; i4 < 8; i4 += 2) {
            float4 ua = *(const float4*)&ush[warp][i4 * 4];
            float4 ub = *(const float4*)&ush[warp][i4 * 4 + 4];
            float4 ca = *(const float4*)&CshT[warp][lane][i4 * 4];
            float4 cb = *(const float4*)&CshT[warp][lane][i4 * 4 + 4];
            float e0 = ex2(ua.x - ca.x - m2);
            float e1 = ex2(ua.y - ca.y - m2);
            float e2 = ex2(ua.z - ca.z - m2);
            float e3 = ex2(ua.w - ca.w - m2);
            float f0 = ex2(ub.x - cb.x - m2);
            float f1 = ex2(ub.y - cb.y - m2);
            float f2 = ex2(ub.z - cb.z - m2);
            float f3 = ex2(ub.w - cb.w - m2);
            s2a += (e0 + e1) + (e2 + e3);
            s2b += (f0 + f1) + (f2 + f3);
            sca += fmaf(e0, ca.x, e1 * ca.y) + fmaf(e2, ca.z, e3 * ca.w);
            scb += fmaf(f0, cb.x, f1 * cb.y) + fmaf(f2, cb.z, f3 * cb.w);
        }
        float s2 = s2a + s2b;
        V = K2LOG - (m2 + lg2(s2));
        redsh[warp][1][t][lane] = NU_TILDE * __fdividef(sca + scb, s2 * SCALE);
    }
    __syncwarp();

    if (lane < 2 * MAX_ITER) {
        const int which = (lane < MAX_ITER) ? 0 : 1;
        const int t = (lane < MAX_ITER) ? lane : lane - MAX_ITER;
        float ssum = 0.f;
#pragma unroll
        for (int i = 0; i < NPTS; i++) ssum += redsh[warp][which][t][i];
        if (which == 0) atomicAdd(&g_err[batch * MAX_ITER + t], ssum);
        else            g_cost[p * MAX_ITER + t] = ssum;
    }
}

// ---------------- fused reduce + finalize (shuffle-based, last-block) --------
__global__ __launch_bounds__(256) void sge_reduce(float* out, int out_size, int E)
{
    __shared__ double wsum[8];
    __shared__ int Tsh[2];
    __shared__ unsigned int lastsh;
    __shared__ float loss_sh;
    const int tid = threadIdx.x, lane = tid & 31, wrp = tid >> 5;
    if (tid < 2) {
        int b = tid;
        int T = MAX_ITER;
        float invE = 1.0f / (float)E;
        for (int t = 0; t < MAX_ITER; t++)
            if (g_err[b * MAX_ITER + t] * invE < THRESH_SCALED) { T = t + 1; break; }
        Tsh[b] = T;
    }
    __syncthreads();
    int p = blockIdx.x * 256 + tid;
    double con = 0.0;
    if (p < 2 * E) {
        int b = (p >= E) ? 1 : 0;
        float c = g_cost[p * MAX_ITER + Tsh[b] - 1];
        float energy = -c;
        con = b ? (double)__expf(energy) : (double)energy * (double)energy;
    }
#pragma unroll
    for (int off = 16; off; off >>= 1)
        con += __shfl_xor_sync(0xffffffffu, con, off);
    if (lane == 0) wsum[wrp] = con;
    __syncthreads();
    if (tid == 0) {
        double bsum = 0.0;
#pragma unroll
        for (int w = 0; w < 8; w++) bsum += wsum[w];
        atomicAdd(&g_accd, bsum);
        __threadfence();
        unsigned int ticket = atomicAdd(&g_done, 1u);
        lastsh = (ticket == (unsigned int)(gridDim.x - 1)) ? 1u : 0u;
        if (lastsh) {
            double total = atomicAdd(&g_accd, 0.0);   // coherent read
            loss_sh = (float)(total / (double)E);
        }
    }
    __syncthreads();
    if (lastsh) {
        for (int i = tid; i < out_size; i += 256) out[i] = loss_sh;
    }
}

// ---------------- launch -----------------------------------------------------
extern "C" void kernel_launch(void* const* d_in, const int* in_sizes, int n_in,
                              void* d_out, int out_size)
{
    const float* x = (const float*)d_in[0];
    const float* W = (const float*)d_in[1];
    const int* ep  = (const int*)d_in[2];
    const int* en  = (const int*)d_in[3];
    int M = in_sizes[0] / FEAT;
    if (M > MAX_NODES) M = MAX_NODES;
    int E = in_sizes[2] / 2;
    if (E > MAX_E) E = MAX_E;

    cudaFuncSetAttribute(sge_gemm_mma,
                         cudaFuncAttributeMaxDynamicSharedMemorySize,
                         2 * STAGE_BYTES);

    int xblocks = (MPAD * FEAT / 4 + 255) / 256;
    sge_convert<<<WBLOCKS + xblocks, 256>>>(x, W, M);
    sge_gemm_mma<<<dim3(EMB / 128, MPAD / 128), 256, 2 * STAGE_BYTES>>>(M);
    int nblocks = (2 * E + PPB - 1) / PPB;
    sge_sinkhorn_pass1<<<nblocks, 128>>>(ep, en, E);
    sge_reduce<<<(2 * E + 255) / 256, 256>>>((float*)d_out, out_size, E);
}